// round 9
// baseline (speedup 1.0000x reference)
#include <cuda_runtime.h>
#include <cuda_fp16.h>
#include <math.h>

#define NCTA   128
#define NTHR   256
#define NWRP   8
#define HID    1024
#define GATES  4096
#define LATENT 2048
#define SEQ    16
// SMEM union: fp16 w_hh slice (32 rows x 1024 halves = 64KB) during recurrence
//             / phase-C h1 staging (SEQ*HID fp32 = 64KB)
#define SMEM_BYTES (64 * 1024)

// ---------------- device scratch (no allocation allowed) ----------------
__device__ float g_xg[SEQ * GATES];   // gate pre-activations, current layer
__device__ float g_h1[SEQ * HID];     // layer-0 hidden outputs (per-step rows)
__device__ __align__(128) unsigned g_bar_line[32];   // g_bar isolated on own line
#define g_bar (g_bar_line[0])

// ------- grid barrier: flip-bit, release/acquire + nanosleep backoff --------
__device__ __forceinline__ void grid_barrier() {
    __syncthreads();
    if (threadIdx.x == 0) {
        unsigned nb = (blockIdx.x == 0) ? (0x80000000u - (NCTA - 1u)) : 1u;
        unsigned old;
        asm volatile("atom.add.release.gpu.global.u32 %0, [%1], %2;"
                     : "=r"(old) : "l"(&g_bar), "r"(nb) : "memory");
        while (true) {
            unsigned cur;
            asm volatile("ld.acquire.gpu.global.u32 %0, [%1];"
                         : "=r"(cur) : "l"(&g_bar) : "memory");
            if ((old ^ cur) & 0x80000000u) break;
            __nanosleep(64);   // back off the hot line
        }
    }
    __syncthreads();
}

__device__ __forceinline__ float sigmoidf_(float x) {
    return 1.0f / (1.0f + __expf(-x));
}
__device__ __forceinline__ float tanhf_fast(float x) {
    return 2.0f / (1.0f + __expf(-2.0f * x)) - 1.0f;
}

// L1-bypassing accessors for cross-CTA mutable data
__device__ __forceinline__ float4 ldcg4(const float4* p) {
    float4 v;
    asm volatile("ld.global.cg.v4.f32 {%0,%1,%2,%3}, [%4];"
                 : "=f"(v.x), "=f"(v.y), "=f"(v.z), "=f"(v.w) : "l"(p) : "memory");
    return v;
}
__device__ __forceinline__ float ldcg1(const float* p) {
    float v;
    asm volatile("ld.global.cg.f32 %0, [%1];" : "=f"(v) : "l"(p) : "memory");
    return v;
}
__device__ __forceinline__ void stcg1(float* p, float v) {
    asm volatile("st.global.cg.f32 [%0], %1;" :: "l"(p), "f"(v) : "memory");
}

// ---------------- input GEMM phase (R6/R8-verbatim arithmetic) --------------
// out[t][row] = inp[t].W[row] + b1 + b2; warp gw owns rows 4gw..4gw+3.
template <int D, bool FROM_SMEM>
__device__ void gate_gemm_dev(const float* __restrict__ W,
                              const float* __restrict__ inp,
                              const float* __restrict__ b1,
                              const float* __restrict__ b2,
                              float* __restrict__ out,
                              float* smem) {
    const int tid  = threadIdx.x;
    const int lane = tid & 31;
    const int warp = tid >> 5;
    const int NF4  = D / 4;

    const float4* xs4;
    if (FROM_SMEM) {
        const float4* in4 = (const float4*)inp;
        float4* s4 = (float4*)smem;
        for (int i = tid; i < SEQ * D / 4; i += NTHR) s4[i] = ldcg4(&in4[i]);
        __syncthreads();
        xs4 = (const float4*)smem;
    } else {
        xs4 = (const float4*)inp;
    }

    const int row = (blockIdx.x * NWRP + warp) * 4;   // 128*8 warps == GATES/4

    float acc[4][SEQ];
#pragma unroll
    for (int r = 0; r < 4; r++)
#pragma unroll
        for (int t = 0; t < SEQ; t++) acc[r][t] = 0.0f;

    const float4* w0 = (const float4*)(W + (size_t)(row + 0) * D);
    const float4* w1 = (const float4*)(W + (size_t)(row + 1) * D);
    const float4* w2 = (const float4*)(W + (size_t)(row + 2) * D);
    const float4* w3 = (const float4*)(W + (size_t)(row + 3) * D);

    for (int ci = lane; ci < NF4; ci += 32) {
        float4 a0 = w0[ci], a1 = w1[ci], a2 = w2[ci], a3 = w3[ci];
#pragma unroll
        for (int t = 0; t < SEQ; t++) {
            float4 xv = xs4[t * NF4 + ci];
            acc[0][t] += a0.x * xv.x + a0.y * xv.y + a0.z * xv.z + a0.w * xv.w;
            acc[1][t] += a1.x * xv.x + a1.y * xv.y + a1.z * xv.z + a1.w * xv.w;
            acc[2][t] += a2.x * xv.x + a2.y * xv.y + a2.z * xv.z + a2.w * xv.w;
            acc[3][t] += a3.x * xv.x + a3.y * xv.y + a3.z * xv.z + a3.w * xv.w;
        }
    }
#pragma unroll
    for (int r = 0; r < 4; r++) {
#pragma unroll
        for (int t = 0; t < SEQ; t++) {
            float s = acc[r][t];
#pragma unroll
            for (int off = 16; off; off >>= 1)
                s += __shfl_xor_sync(0xffffffffu, s, off);
            if (lane == 0)
                stcg1(&out[t * GATES + row + r], s + b1[row + r] + b2[row + r]);
        }
    }
}

// ---------------- one LSTM layer: fp16 weights SMEM-resident ---------------
// CTA owns 8 units j = blockIdx*8 + warp. Its 32 gate rows are converted to
// fp16 in SMEM once per layer (64KB -> half the per-step LSU bytes of fp32).
// Per step: 8 direct ld.cg.v4 of h, 16 conflict-free LDS.128 of weights,
// fp32 accumulation, shuffle reduce, lane-0 pointwise (fast tanh), st.cg.
__device__ void lstm_layer_dev(const float* __restrict__ whh,
                               const float* __restrict__ xg,
                               float* __restrict__ hbase,     // SEQ rows out
                               float* __restrict__ last_out,  // null or HID
                               __half* wh) {
    const int lane = threadIdx.x & 31;
    const int warp = threadIdx.x >> 5;
    const int j    = blockIdx.x * NWRP + warp;

    // convert this CTA's w_hh slice: smem row r = w*4+g  <->  global row
    // g*HID + (blockIdx*8+w)   (R7-proven mapping, fp16 payload)
    for (int idx = threadIdx.x; idx < 32 * HID; idx += NTHR) {
        int r = idx >> 10, k = idx & 1023;
        int w = r >> 2, g = r & 3;
        wh[idx] = __float2half(
            __ldg(&whh[(size_t)(g * HID + (blockIdx.x * NWRP + w)) * HID + k]));
    }
    __syncthreads();

    // preload this unit's 4 gate biases for all 16 steps: lane t holds step t
    float xgi = 0.f, xgf = 0.f, xgg = 0.f, xgo = 0.f;
    if (lane < SEQ) {
        const float* xgt = xg + lane * GATES;
        xgi = ldcg1(&xgt[0 * HID + j]);
        xgf = ldcg1(&xgt[1 * HID + j]);
        xgg = ldcg1(&xgt[2 * HID + j]);
        xgo = ldcg1(&xgt[3 * HID + j]);
    }

    const uint4* w0 = (const uint4*)(wh + (warp * 4 + 0) * HID);
    const uint4* w1 = (const uint4*)(wh + (warp * 4 + 1) * HID);
    const uint4* w2 = (const uint4*)(wh + (warp * 4 + 2) * HID);
    const uint4* w3 = (const uint4*)(wh + (warp * 4 + 3) * HID);

    float c = 0.0f;
    for (int t = 0; t < SEQ; t++) {
        float dot[4] = {0.f, 0.f, 0.f, 0.f};
        if (t > 0) {
            // h elements 8*(lane+32q)+i, i<8: matches uint4 weight chunks
            const float4* hp4 = (const float4*)(hbase + (t - 1) * HID);
            float hreg[32];
#pragma unroll
            for (int q = 0; q < 4; q++) {
                float4 a = ldcg4(&hp4[2 * (lane + 32 * q)]);
                float4 b = ldcg4(&hp4[2 * (lane + 32 * q) + 1]);
                hreg[q * 8 + 0] = a.x; hreg[q * 8 + 1] = a.y;
                hreg[q * 8 + 2] = a.z; hreg[q * 8 + 3] = a.w;
                hreg[q * 8 + 4] = b.x; hreg[q * 8 + 5] = b.y;
                hreg[q * 8 + 6] = b.z; hreg[q * 8 + 7] = b.w;
            }

            float s0 = 0.f, s1 = 0.f, s2 = 0.f, s3 = 0.f;
#pragma unroll
            for (int q = 0; q < 4; q++) {
                uint4 va = w0[lane + 32 * q];
                uint4 vb = w1[lane + 32 * q];
                uint4 vc = w2[lane + 32 * q];
                uint4 vd = w3[lane + 32 * q];
                const __half2* ha = (const __half2*)&va;
                const __half2* hb = (const __half2*)&vb;
                const __half2* hc = (const __half2*)&vc;
                const __half2* hd = (const __half2*)&vd;
#pragma unroll
                for (int i = 0; i < 4; i++) {
                    float2 fa = __half22float2(ha[i]);
                    float2 fb = __half22float2(hb[i]);
                    float2 fc = __half22float2(hc[i]);
                    float2 fd = __half22float2(hd[i]);
                    float he = hreg[q * 8 + 2 * i];
                    float ho = hreg[q * 8 + 2 * i + 1];
                    s0 += fa.x * he + fa.y * ho;
                    s1 += fb.x * he + fb.y * ho;
                    s2 += fc.x * he + fc.y * ho;
                    s3 += fd.x * he + fd.y * ho;
                }
            }
            dot[0] = s0; dot[1] = s1; dot[2] = s2; dot[3] = s3;
#pragma unroll
            for (int g = 0; g < 4; g++)
#pragma unroll
                for (int off = 16; off; off >>= 1)
                    dot[g] += __shfl_xor_sync(0xffffffffu, dot[g], off);
        }

        // step-t biases by shuffle from lane t (all lanes converged)
        float bi = __shfl_sync(0xffffffffu, xgi, t);
        float bf = __shfl_sync(0xffffffffu, xgf, t);
        float bg = __shfl_sync(0xffffffffu, xgg, t);
        float bo = __shfl_sync(0xffffffffu, xgo, t);

        if (lane == 0) {
            float iv = sigmoidf_(bi + dot[0]);
            float fv = sigmoidf_(bf + dot[1]);
            float gv = tanhf_fast(bg + dot[2]);
            float ov = sigmoidf_(bo + dot[3]);
            float cn = fv * c + iv * gv;
            c = cn;
            float hval = ov * tanhf_fast(cn);
            stcg1(&hbase[t * HID + j], hval);
            if (last_out && t == SEQ - 1) stcg1(&last_out[j], hval);
        }
        // publish h_t; very last step of the final layer needs no barrier
        if (!(last_out && t == SEQ - 1)) grid_barrier();
    }
}

// ---------------- single persistent kernel ----------------------------------
__global__ void __launch_bounds__(NTHR, 1)
lstm2_persist(const float* __restrict__ x,
              const float* __restrict__ w_ih0, const float* __restrict__ w_hh0,
              const float* __restrict__ b_ih0, const float* __restrict__ b_hh0,
              const float* __restrict__ w_ih1, const float* __restrict__ w_hh1,
              const float* __restrict__ b_ih1, const float* __restrict__ b_hh1,
              float* __restrict__ out) {
    extern __shared__ float smem[];
    __half* wh = (__half*)smem;

    // Phase A: xg = x @ w_ih0^T + b_ih0 + b_hh0   (x immutable -> plain LDG)
    gate_gemm_dev<LATENT, false>(w_ih0, x, b_ih0, b_hh0, g_xg, smem);
    grid_barrier();

    // Layer 0 recurrence (w_hh0 fp16 slice in SMEM)
    lstm_layer_dev(w_hh0, g_xg, g_h1, nullptr, wh);

    // Phase C: xg = h1 @ w_ih1^T + b_ih1 + b_hh1 (h1 staged into same SMEM;
    // layer-0 weights dead; grid_barrier's syncthreads ordered the reuse)
    gate_gemm_dev<HID, true>(w_ih1, g_h1, b_ih1, b_hh1, g_xg, smem);
    grid_barrier();

    // Layer 1 recurrence -> out: [0:HID) last_output, [HID:) h2 rows
    lstm_layer_dev(w_hh1, g_xg, out + HID, out, wh);
}

// ---------------- host launch (graph-capturable, single node) ---------------
extern "C" void kernel_launch(void* const* d_in, const int* in_sizes, int n_in,
                              void* d_out, int out_size) {
    const float* x     = (const float*)d_in[0];
    const float* w_ih0 = (const float*)d_in[1];
    const float* w_hh0 = (const float*)d_in[2];
    const float* b_ih0 = (const float*)d_in[3];
    const float* b_hh0 = (const float*)d_in[4];
    const float* w_ih1 = (const float*)d_in[5];
    const float* w_hh1 = (const float*)d_in[6];
    const float* b_ih1 = (const float*)d_in[7];
    const float* b_hh1 = (const float*)d_in[8];
    float* out = (float*)d_out;

    cudaFuncSetAttribute(lstm2_persist,
                         cudaFuncAttributeMaxDynamicSharedMemorySize, SMEM_BYTES);
    lstm2_persist<<<NCTA, NTHR, SMEM_BYTES>>>(x, w_ih0, w_hh0, b_ih0, b_hh0,
                                              w_ih1, w_hh1, b_ih1, b_hh1, out);
}

// round 12
// speedup vs baseline: 1.2190x; 1.2190x over previous
#include <cuda_runtime.h>
#include <math.h>

#define NCTA   128
#define NTHR   256
#define NWRP   8
#define HID    1024
#define GATES  4096
#define LATENT 2048
#define SEQ    16
// 128KB: per-CTA w_hh slice (32 rows x 1024 fp32) during recurrence,
// reused as phase-C h1 staging (64KB) between layers.
#define SMEM_BYTES (32 * 1024 * 4)

// ---------------- device scratch (no allocation allowed) ----------------
__device__ float g_xg[SEQ * GATES];   // gate pre-activations, current layer
__device__ float g_h1[SEQ * HID];     // layer-0 hidden outputs (per-step rows)
__device__ __align__(128) unsigned g_bar_line[32];
#define g_bar (g_bar_line[0])

// ---- grid barrier: flip-bit; release-RMW arrival, RELAXED poll + one
// acquire fence after detection (keeps strong ops off the hot line) --------
__device__ __forceinline__ void grid_barrier() {
    __syncthreads();
    if (threadIdx.x == 0) {
        unsigned nb = (blockIdx.x == 0) ? (0x80000000u - (NCTA - 1u)) : 1u;
        unsigned old;
        asm volatile("atom.add.release.gpu.global.u32 %0, [%1], %2;"
                     : "=r"(old) : "l"(&g_bar), "r"(nb) : "memory");
        while (true) {
            unsigned cur;
            asm volatile("ld.relaxed.gpu.global.u32 %0, [%1];"
                         : "=r"(cur) : "l"(&g_bar) : "memory");
            if ((old ^ cur) & 0x80000000u) break;
            __nanosleep(32);
        }
        asm volatile("fence.acq_rel.gpu;" ::: "memory");
    }
    __syncthreads();
}

__device__ __forceinline__ float sigmoidf_(float x) {
    return 1.0f / (1.0f + __expf(-x));
}

// L1-bypassing accessors for cross-CTA mutable data
__device__ __forceinline__ float4 ldcg4(const float4* p) {
    float4 v;
    asm volatile("ld.global.cg.v4.f32 {%0,%1,%2,%3}, [%4];"
                 : "=f"(v.x), "=f"(v.y), "=f"(v.z), "=f"(v.w) : "l"(p) : "memory");
    return v;
}
__device__ __forceinline__ float ldcg1(const float* p) {
    float v;
    asm volatile("ld.global.cg.f32 %0, [%1];" : "=f"(v) : "l"(p) : "memory");
    return v;
}
__device__ __forceinline__ void stcg1(float* p, float v) {
    asm volatile("st.global.cg.f32 [%0], %1;" :: "l"(p), "f"(v) : "memory");
}

// ---------------- input GEMM phase (R6/R8-verbatim arithmetic) --------------
// out[t][row] = inp[t].W[row] + b1 + b2; warp gw owns rows 4gw..4gw+3.
template <int D, bool FROM_SMEM>
__device__ void gate_gemm_dev(const float* __restrict__ W,
                              const float* __restrict__ inp,
                              const float* __restrict__ b1,
                              const float* __restrict__ b2,
                              float* __restrict__ out,
                              float* smem) {
    const int tid  = threadIdx.x;
    const int lane = tid & 31;
    const int warp = tid >> 5;
    const int NF4  = D / 4;

    const float4* xs4;
    if (FROM_SMEM) {
        const float4* in4 = (const float4*)inp;
        float4* s4 = (float4*)smem;
        for (int i = tid; i < SEQ * D / 4; i += NTHR) s4[i] = ldcg4(&in4[i]);
        __syncthreads();
        xs4 = (const float4*)smem;
    } else {
        xs4 = (const float4*)inp;
    }

    const int row = (blockIdx.x * NWRP + warp) * 4;   // 128*8 warps == GATES/4

    float acc[4][SEQ];
#pragma unroll
    for (int r = 0; r < 4; r++)
#pragma unroll
        for (int t = 0; t < SEQ; t++) acc[r][t] = 0.0f;

    const float4* w0 = (const float4*)(W + (size_t)(row + 0) * D);
    const float4* w1 = (const float4*)(W + (size_t)(row + 1) * D);
    const float4* w2 = (const float4*)(W + (size_t)(row + 2) * D);
    const float4* w3 = (const float4*)(W + (size_t)(row + 3) * D);

    for (int ci = lane; ci < NF4; ci += 32) {
        float4 a0 = w0[ci], a1 = w1[ci], a2 = w2[ci], a3 = w3[ci];
#pragma unroll
        for (int t = 0; t < SEQ; t++) {
            float4 xv = xs4[t * NF4 + ci];
            acc[0][t] += a0.x * xv.x + a0.y * xv.y + a0.z * xv.z + a0.w * xv.w;
            acc[1][t] += a1.x * xv.x + a1.y * xv.y + a1.z * xv.z + a1.w * xv.w;
            acc[2][t] += a2.x * xv.x + a2.y * xv.y + a2.z * xv.z + a2.w * xv.w;
            acc[3][t] += a3.x * xv.x + a3.y * xv.y + a3.z * xv.z + a3.w * xv.w;
        }
    }
#pragma unroll
    for (int r = 0; r < 4; r++) {
#pragma unroll
        for (int t = 0; t < SEQ; t++) {
            float s = acc[r][t];
#pragma unroll
            for (int off = 16; off; off >>= 1)
                s += __shfl_xor_sync(0xffffffffu, s, off);
            if (lane == 0)
                stcg1(&out[t * GATES + row + r], s + b1[row + r] + b2[row + r]);
        }
    }
}

// ---------------- one LSTM layer: SMEM-resident fp32 weights ----------------
// CTA owns units j = blockIdx*8 + warp. Its 32 gate rows (128KB fp32) are
// staged once per layer into SMEM -> per-step GEMV never touches L1/L2 and is
// immune to the barrier's gpu-scope L1 invalidation. Per step: 8 direct
// ld.cg.v4 of h, 16 conflict-free LDS.128 weight reads, R6-exact fp32
// accumulation, shuffle reduce, lane-0 pointwise, st.cg publish, barrier.
__device__ void lstm_layer_dev(const float* __restrict__ whh,
                               const float* __restrict__ xg,
                               float* __restrict__ hbase,     // SEQ rows out
                               float* __restrict__ last_out,  // null or HID
                               float* wbuf) {
    const int lane = threadIdx.x & 31;
    const int warp = threadIdx.x >> 5;
    const int base = blockIdx.x * NWRP;
    const int j    = base + warp;

    // stage w_hh slice (float4): smem row r = w*4+g <-> global row g*HID+(base+w)
    {
        float4* wb4 = (float4*)wbuf;
        for (int idx4 = threadIdx.x; idx4 < 32 * HID / 4; idx4 += NTHR) {
            int r = idx4 >> 8, k4 = idx4 & 255;
            int w = r >> 2, g = r & 3;
            wb4[idx4] = ((const float4*)(whh + (size_t)(g * HID + base + w) * HID))[k4];
        }
    }
    __syncthreads();

    // preload this unit's 4 gate biases for all 16 steps: lane t holds step t
    float xgi = 0.f, xgf = 0.f, xgg = 0.f, xgo = 0.f;
    if (lane < SEQ) {
        const float* xgt = xg + lane * GATES;
        xgi = ldcg1(&xgt[0 * HID + j]);
        xgf = ldcg1(&xgt[1 * HID + j]);
        xgg = ldcg1(&xgt[2 * HID + j]);
        xgo = ldcg1(&xgt[3 * HID + j]);
    }

    const float4* w0 = (const float4*)(wbuf + (warp * 4 + 0) * HID);
    const float4* w1 = (const float4*)(wbuf + (warp * 4 + 1) * HID);
    const float4* w2 = (const float4*)(wbuf + (warp * 4 + 2) * HID);
    const float4* w3 = (const float4*)(wbuf + (warp * 4 + 3) * HID);

    float c = 0.0f;
    for (int t = 0; t < SEQ; t++) {
        float dot[4] = {0.f, 0.f, 0.f, 0.f};
        if (t > 0) {
            const float4* hp4 = (const float4*)(hbase + (t - 1) * HID);
            float4 hv[8];
#pragma unroll
            for (int q = 0; q < 8; q++) hv[q] = ldcg4(&hp4[lane + 32 * q]);

            float s0 = 0.f, s1 = 0.f, s2 = 0.f, s3 = 0.f;
#pragma unroll
            for (int q = 0; q < 8; q++) {
                float4 a0 = w0[lane + 32 * q];
                float4 a1 = w1[lane + 32 * q];
                float4 a2 = w2[lane + 32 * q];
                float4 a3 = w3[lane + 32 * q];
                s0 += a0.x * hv[q].x + a0.y * hv[q].y + a0.z * hv[q].z + a0.w * hv[q].w;
                s1 += a1.x * hv[q].x + a1.y * hv[q].y + a1.z * hv[q].z + a1.w * hv[q].w;
                s2 += a2.x * hv[q].x + a2.y * hv[q].y + a2.z * hv[q].z + a2.w * hv[q].w;
                s3 += a3.x * hv[q].x + a3.y * hv[q].y + a3.z * hv[q].z + a3.w * hv[q].w;
            }
            dot[0] = s0; dot[1] = s1; dot[2] = s2; dot[3] = s3;
#pragma unroll
            for (int g = 0; g < 4; g++)
#pragma unroll
                for (int off = 16; off; off >>= 1)
                    dot[g] += __shfl_xor_sync(0xffffffffu, dot[g], off);
        }

        // step-t biases by shuffle from lane t (all lanes converged here)
        float bi = __shfl_sync(0xffffffffu, xgi, t);
        float bf = __shfl_sync(0xffffffffu, xgf, t);
        float bg = __shfl_sync(0xffffffffu, xgg, t);
        float bo = __shfl_sync(0xffffffffu, xgo, t);

        if (lane == 0) {
            float iv = sigmoidf_(bi + dot[0]);
            float fv = sigmoidf_(bf + dot[1]);
            float gv = tanhf(bg + dot[2]);
            float ov = sigmoidf_(bo + dot[3]);
            float cn = fv * c + iv * gv;
            c = cn;
            float hval = ov * tanhf(cn);
            stcg1(&hbase[t * HID + j], hval);
            if (last_out && t == SEQ - 1) stcg1(&last_out[j], hval);
        }
        // publish h_t; very last step of the final layer needs no barrier
        if (!(last_out && t == SEQ - 1)) grid_barrier();
    }
}

// ---------------- single persistent kernel ----------------------------------
__global__ void __launch_bounds__(NTHR, 1)
lstm2_persist(const float* __restrict__ x,
              const float* __restrict__ w_ih0, const float* __restrict__ w_hh0,
              const float* __restrict__ b_ih0, const float* __restrict__ b_hh0,
              const float* __restrict__ w_ih1, const float* __restrict__ w_hh1,
              const float* __restrict__ b_ih1, const float* __restrict__ b_hh1,
              float* __restrict__ out) {
    extern __shared__ float smem[];

    // Phase A: xg = x @ w_ih0^T + b_ih0 + b_hh0   (x immutable -> plain LDG)
    gate_gemm_dev<LATENT, false>(w_ih0, x, b_ih0, b_hh0, g_xg, smem);
    grid_barrier();

    // Layer 0 recurrence (w_hh0 staged into smem; barrier after each step
    // including t=15, which orders g_h1 for phase C)
    lstm_layer_dev(w_hh0, g_xg, g_h1, nullptr, smem);

    // Phase C: xg = h1 @ w_ih1^T + b_ih1 + b_hh1 (h1 staged into same smem;
    // layer-0 weights dead; barrier's syncthreads ordered the reuse)
    gate_gemm_dev<HID, true>(w_ih1, g_h1, b_ih1, b_hh1, g_xg, smem);
    grid_barrier();

    // Layer 1 recurrence -> out: [0:HID) last_output, [HID:) h2 rows
    lstm_layer_dev(w_hh1, g_xg, out + HID, out, smem);
}

// ---------------- host launch (graph-capturable, single node) ---------------
extern "C" void kernel_launch(void* const* d_in, const int* in_sizes, int n_in,
                              void* d_out, int out_size) {
    const float* x     = (const float*)d_in[0];
    const float* w_ih0 = (const float*)d_in[1];
    const float* w_hh0 = (const float*)d_in[2];
    const float* b_ih0 = (const float*)d_in[3];
    const float* b_hh0 = (const float*)d_in[4];
    const float* w_ih1 = (const float*)d_in[5];
    const float* w_hh1 = (const float*)d_in[6];
    const float* b_ih1 = (const float*)d_in[7];
    const float* b_hh1 = (const float*)d_in[8];
    float* out = (float*)d_out;

    cudaFuncSetAttribute(lstm2_persist,
                         cudaFuncAttributeMaxDynamicSharedMemorySize, SMEM_BYTES);
    lstm2_persist<<<NCTA, NTHR, SMEM_BYTES>>>(x, w_ih0, w_hh0, b_ih0, b_hh0,
                                              w_ih1, w_hh1, b_ih1, b_hh1, out);
}